// round 12
// baseline (speedup 1.0000x reference)
#include <cuda_runtime.h>
#include <cuda_bf16.h>
#include <cuda_fp16.h>
#include <cstdint>

#define NN 50000
#define NE 600000
#define D  128
#define NL 6
#define MT 128
#define NTILES ((NN + MT - 1) / MT)   // 391
#define SREG 136                      // smem row stride in bf16 (128 + 8 pad)
#define SCAN_BLKS ((NN + 255) / 256)  // 196

// ---------------- scratch (device globals; no allocation allowed) ----------------
__device__ float g_h[NN * D];                    // fp32 hidden (final layer only, for FC)
__device__ __half g_hf[NN * D];                  // fp16 gather operand (x, then hidden)
__device__ __nv_bfloat16 g_Ahi[NN * 256];        // A = [agg | h] bf16 hi
__device__ __nv_bfloat16 g_Alo[NN * 256];        // A lo residual
__device__ __nv_bfloat16 g_Bhi[NL * 128 * 256];  // B[n][k] = W[k][n], bf16 hi
__device__ __nv_bfloat16 g_Blo[NL * 128 * 256];  // lo residual
__device__ int g_rowptr[NN + 1];
__device__ int g_cursor[NN];
__device__ int g_deg[NN];
__device__ int g_esrc[NE];
__device__ int g_psum[256];                      // per-block partial sums (196 used)

// ---------------- helpers ----------------
__device__ __forceinline__ void mma16816(float* c, const uint32_t* a, const uint32_t* b) {
    asm volatile("mma.sync.aligned.m16n8k16.row.col.f32.bf16.bf16.f32 "
                 "{%0,%1,%2,%3}, {%4,%5,%6,%7}, {%8,%9}, {%0,%1,%2,%3};"
                 : "+f"(c[0]), "+f"(c[1]), "+f"(c[2]), "+f"(c[3])
                 : "r"(a[0]), "r"(a[1]), "r"(a[2]), "r"(a[3]), "r"(b[0]), "r"(b[1]));
}
__device__ __forceinline__ uint32_t pack_bf2(float x, float y) {
    __nv_bfloat162 h = __float22bfloat162_rn(make_float2(x, y));
    return *(uint32_t*)&h;
}
// split pair (x,y) -> hi packed, lo packed
__device__ __forceinline__ void split2(float x, float y, uint32_t& hi, uint32_t& lo) {
    __nv_bfloat16 hx = __float2bfloat16(x);
    __nv_bfloat16 hy = __float2bfloat16(y);
    hi = pack_bf2(x, y);
    lo = pack_bf2(x - __bfloat162float(hx), y - __bfloat162float(hy));
}

// ---------------- CSR construction ----------------
__global__ void k_zero_deg() {
    int i = blockIdx.x * blockDim.x + threadIdx.x;
    if (i < NN) g_deg[i] = 0;
}
__global__ void k_count(const int* __restrict__ ei) {
    int i = blockIdx.x * blockDim.x + threadIdx.x;
    if (i < NE) atomicAdd(&g_deg[ei[NE + i]], 1);
}
// pass A: per-block totals of 256 degrees
__global__ void k_scanA() {
    __shared__ int ws[8];
    int tid = threadIdx.x, lane = tid & 31, wid = tid >> 5;
    int i = blockIdx.x * 256 + tid;
    int v = (i < NN) ? g_deg[i] : 0;
    #pragma unroll
    for (int d2 = 16; d2; d2 >>= 1) v += __shfl_xor_sync(0xffffffffu, v, d2);
    if (lane == 0) ws[wid] = v;
    __syncthreads();
    if (tid == 0) {
        int s = 0;
        #pragma unroll
        for (int j = 0; j < 8; j++) s += ws[j];
        g_psum[blockIdx.x] = s;
    }
}
// pass B: one block scans the partials into exclusive offsets
__global__ void k_scanB() {
    __shared__ int ws[8];
    int tid = threadIdx.x, lane = tid & 31, wid = tid >> 5;
    int v = (tid < SCAN_BLKS) ? g_psum[tid] : 0;
    int incl = v;
    #pragma unroll
    for (int d2 = 1; d2 < 32; d2 <<= 1) {
        int t = __shfl_up_sync(0xffffffffu, incl, d2);
        if (lane >= d2) incl += t;
    }
    if (lane == 31) ws[wid] = incl;
    __syncthreads();
    if (wid == 0 && lane < 8) {
        int s = ws[lane];
        int x2 = s;
        #pragma unroll
        for (int d2 = 1; d2 < 8; d2 <<= 1) {
            int t = __shfl_up_sync(0xffu, x2, d2);
            if (lane >= d2) x2 += t;
        }
        ws[lane] = x2 - s;   // exclusive warp offsets
    }
    __syncthreads();
    if (tid < SCAN_BLKS) g_psum[tid] = incl - v + ws[wid];  // exclusive prefix
    if (tid == 0) g_rowptr[0] = 0;
}
// pass C: intra-block scan + block offset -> rowptr, cursor
__global__ void k_scanC() {
    __shared__ int ws[8];
    int tid = threadIdx.x, lane = tid & 31, wid = tid >> 5;
    int i = blockIdx.x * 256 + tid;
    int v = (i < NN) ? g_deg[i] : 0;
    int incl = v;
    #pragma unroll
    for (int d2 = 1; d2 < 32; d2 <<= 1) {
        int t = __shfl_up_sync(0xffffffffu, incl, d2);
        if (lane >= d2) incl += t;
    }
    if (lane == 31) ws[wid] = incl;
    __syncthreads();
    if (wid == 0 && lane < 8) {
        int s = ws[lane];
        int x2 = s;
        #pragma unroll
        for (int d2 = 1; d2 < 8; d2 <<= 1) {
            int t = __shfl_up_sync(0xffu, x2, d2);
            if (lane >= d2) x2 += t;
        }
        ws[lane] = x2 - s;
    }
    __syncthreads();
    if (i < NN) {
        int base = g_psum[blockIdx.x] + ws[wid];
        g_rowptr[i + 1] = base + incl;
        g_cursor[i] = base + incl - v;
    }
}
__global__ void k_fill(const int* __restrict__ ei) {
    int i = blockIdx.x * blockDim.x + threadIdx.x;
    if (i < NE) {
        int dst = ei[NE + i];
        int pos = atomicAdd(&g_cursor[dst], 1);
        g_esrc[pos] = ei[i];
    }
}

// ---------------- weight transpose + split (once per launch) ----------------
__global__ void k_prepw(const float* __restrict__ Wl, const float* __restrict__ Wr) {
    int idx = blockIdx.x * blockDim.x + threadIdx.x;
    if (idx >= NL * 128 * 256) return;
    int l = idx >> 15;
    int r = idx & 32767;
    int n = r >> 8;
    int k = r & 255;
    const float* W = (k < D) ? (Wl + (long)l * D * D) : (Wr + (long)l * D * D);
    float v = __ldg(&W[(k & 127) * D + n]);
    __nv_bfloat16 hi = __float2bfloat16(v);
    g_Bhi[idx] = hi;
    g_Blo[idx] = __float2bfloat16(v - __bfloat162float(hi));
}

// ---------------- prep x: fp16 copy for gathering + split into A cols [128,256) ----------------
__global__ void k_prepx(const float* __restrict__ x) {
    int idx = blockIdx.x * blockDim.x + threadIdx.x;
    if (idx >= NN * 32) return;
    int row = idx >> 5;
    int c = (idx & 31) << 2;
    float4 v = __ldg((const float4*)(x + (long)row * D + c));
    __half2 f0 = __float22half2_rn(make_float2(v.x, v.y));
    __half2 f1 = __float22half2_rn(make_float2(v.z, v.w));
    uint32_t* pf = (uint32_t*)(g_hf + (long)row * D + c);
    pf[0] = *(uint32_t*)&f0;
    pf[1] = *(uint32_t*)&f1;
    uint32_t h0, l0, h1, l1;
    split2(v.x, v.y, h0, l0);
    split2(v.z, v.w, h1, l1);
    uint32_t* ph = (uint32_t*)(g_Ahi + (long)row * 256 + 128 + c);
    uint32_t* pl = (uint32_t*)(g_Alo + (long)row * 256 + 128 + c);
    ph[0] = h0; ph[1] = h1;
    pl[0] = l0; pl[1] = l1;
}

// ---------------- mean aggregation: warp per node, predicated batch-16 gather ----------------
// Single fp16 path (g_hf holds fp16(x) for layer 0, fp16 hidden after).
__global__ void __launch_bounds__(256)
k_agg() {
    int gw = (blockIdx.x * blockDim.x + threadIdx.x) >> 5;
    if (gw >= NN) return;
    int lane = threadIdx.x & 31;
    int beg = g_rowptr[gw], end = g_rowptr[gw + 1];
    float ax = 0.f, ay = 0.f, az = 0.f, aw = 0.f;
    for (int e0 = beg; e0 < end; e0 += 16) {
        uint2 u[16];
        #pragma unroll
        for (int j = 0; j < 16; j++) {
            u[j] = make_uint2(0u, 0u);
            if (e0 + j < end) {
                int s = __ldg(&g_esrc[e0 + j]);
                u[j] = __ldg((const uint2*)(g_hf + (long)s * D) + lane);
            }
        }
        #pragma unroll
        for (int j = 0; j < 16; j++) {
            float2 a = __half22float2(*(__half2*)&u[j].x);
            float2 b = __half22float2(*(__half2*)&u[j].y);
            ax += a.x; ay += a.y; az += b.x; aw += b.y;
        }
    }
    float inv = 1.0f / fmaxf((float)(end - beg), 1.0f);
    ax *= inv; ay *= inv; az *= inv; aw *= inv;
    uint32_t h0, l0, h1, l1;
    split2(ax, ay, h0, l0);
    split2(az, aw, h1, l1);
    int off = lane << 2;
    uint32_t* ph = (uint32_t*)(g_Ahi + (long)gw * 256 + off);
    uint32_t* pl = (uint32_t*)(g_Alo + (long)gw * 256 + off);
    ph[0] = h0; ph[1] = h1;
    pl[0] = l0; pl[1] = l1;
}

// ---------------- tensor-core GEMM: h = relu(A @ B^T + bl) ----------------
// 256 threads = 8 warps, warp grid 2(m) x 4(n), warp tile 64x32, frag m16n8k16.
// 3-term bf16 split: hihi + hilo + lohi. Direct LDS.32 fragment loads (R6-proven).
#define SM_A_HI 0
#define SM_A_LO (128 * SREG)
#define SM_B_HI (2 * 128 * SREG)
#define SM_B_LO (3 * 128 * SREG)
#define SM_TOT_BF (4 * 128 * SREG)   // 69632 bf16 = 139264 bytes

__global__ void __launch_bounds__(256, 1)
k_gemm_mma(int layer, int write_split, const float* __restrict__ bl) {
    extern __shared__ __nv_bfloat16 smem[];
    __nv_bfloat16* sAhi = smem + SM_A_HI;
    __nv_bfloat16* sAlo = smem + SM_A_LO;
    __nv_bfloat16* sBhi = smem + SM_B_HI;
    __nv_bfloat16* sBlo = smem + SM_B_LO;

    int tid = threadIdx.x;
    int lane = tid & 31, wid = tid >> 5;
    int warp_m = wid >> 2, warp_n = wid & 3;
    int m0 = blockIdx.x * MT;
    int g = lane >> 2, t = lane & 3;

    float acc[4][4][4];
    #pragma unroll
    for (int i = 0; i < 4; i++)
        #pragma unroll
        for (int j = 0; j < 4; j++)
            #pragma unroll
            for (int p = 0; p < 4; p++) acc[i][j][p] = 0.f;

    const __nv_bfloat16* gB_hi = g_Bhi + (long)layer * 128 * 256;
    const __nv_bfloat16* gB_lo = g_Blo + (long)layer * 128 * 256;

    #pragma unroll 1
    for (int chunk = 0; chunk < 2; chunk++) {
        int kbase = chunk << 7;
        if (chunk) __syncthreads();
        // stage A hi/lo (row-guarded) and B hi/lo, 16B per thread per iter
        #pragma unroll
        for (int i = 0; i < 8; i++) {
            int lin = tid + i * 256;
            int row = lin >> 4;
            int c8 = (lin & 15) << 3;
            uint4 vh = make_uint4(0, 0, 0, 0), vl = vh;
            int gr = m0 + row;
            if (gr < NN) {
                vh = *(const uint4*)(g_Ahi + (long)gr * 256 + kbase + c8);
                vl = *(const uint4*)(g_Alo + (long)gr * 256 + kbase + c8);
            }
            *(uint4*)(sAhi + row * SREG + c8) = vh;
            *(uint4*)(sAlo + row * SREG + c8) = vl;
            uint4 bh = *(const uint4*)(gB_hi + (long)row * 256 + kbase + c8);
            uint4 blv = *(const uint4*)(gB_lo + (long)row * 256 + kbase + c8);
            *(uint4*)(sBhi + row * SREG + c8) = bh;
            *(uint4*)(sBlo + row * SREG + c8) = blv;
        }
        __syncthreads();

        #pragma unroll
        for (int ks = 0; ks < 8; ks++) {
            int kcol = (ks << 4) + (t << 1);
            uint32_t ahi[4][4], alo[4][4];
            #pragma unroll
            for (int mf = 0; mf < 4; mf++) {
                int r = warp_m * 64 + mf * 16 + g;
                ahi[mf][0] = *(const uint32_t*)(sAhi + r * SREG + kcol);
                ahi[mf][1] = *(const uint32_t*)(sAhi + (r + 8) * SREG + kcol);
                ahi[mf][2] = *(const uint32_t*)(sAhi + r * SREG + kcol + 8);
                ahi[mf][3] = *(const uint32_t*)(sAhi + (r + 8) * SREG + kcol + 8);
                alo[mf][0] = *(const uint32_t*)(sAlo + r * SREG + kcol);
                alo[mf][1] = *(const uint32_t*)(sAlo + (r + 8) * SREG + kcol);
                alo[mf][2] = *(const uint32_t*)(sAlo + r * SREG + kcol + 8);
                alo[mf][3] = *(const uint32_t*)(sAlo + (r + 8) * SREG + kcol + 8);
            }
            uint32_t bhi[4][2], blo[4][2];
            #pragma unroll
            for (int nf = 0; nf < 4; nf++) {
                int nr = warp_n * 32 + nf * 8 + g;
                bhi[nf][0] = *(const uint32_t*)(sBhi + nr * SREG + kcol);
                bhi[nf][1] = *(const uint32_t*)(sBhi + nr * SREG + kcol + 8);
                blo[nf][0] = *(const uint32_t*)(sBlo + nr * SREG + kcol);
                blo[nf][1] = *(const uint32_t*)(sBlo + nr * SREG + kcol + 8);
            }
            #pragma unroll
            for (int mf = 0; mf < 4; mf++)
                #pragma unroll
                for (int nf = 0; nf < 4; nf++) {
                    mma16816(acc[mf][nf], ahi[mf], bhi[nf]);
                    mma16816(acc[mf][nf], ahi[mf], blo[nf]);
                    mma16816(acc[mf][nf], alo[mf], bhi[nf]);
                }
        }
    }

    // epilogue: bias + relu.
    // layers 0-4 (write_split): store fp16 gather copy + bf16 split A cols [128,256)
    // last layer: store fp32 g_h for the FC
    #pragma unroll
    for (int nf = 0; nf < 4; nf++) {
        int col = warp_n * 32 + nf * 8 + (t << 1);
        float b0 = __ldg(&bl[col]);
        float b1 = __ldg(&bl[col + 1]);
        #pragma unroll
        for (int mf = 0; mf < 4; mf++) {
            int r0 = m0 + warp_m * 64 + mf * 16 + g;
            #pragma unroll
            for (int half = 0; half < 2; half++) {
                int r = r0 + half * 8;
                if (r < NN) {
                    float o0 = fmaxf(acc[mf][nf][half * 2 + 0] + b0, 0.f);
                    float o1 = fmaxf(acc[mf][nf][half * 2 + 1] + b1, 0.f);
                    if (write_split) {
                        __half2 hf = __float22half2_rn(make_float2(o0, o1));
                        *(uint32_t*)(g_hf + (long)r * D + col) = *(uint32_t*)&hf;
                        uint32_t hp, lp;
                        split2(o0, o1, hp, lp);
                        *(uint32_t*)(g_Ahi + (long)r * 256 + 128 + col) = hp;
                        *(uint32_t*)(g_Alo + (long)r * 256 + 128 + col) = lp;
                    } else {
                        *(float2*)(g_h + (long)r * D + col) = make_float2(o0, o1);
                    }
                }
            }
        }
    }
}

// ---------------- final FC [128 -> 2]: warp per node ----------------
__global__ void k_fc(const float* __restrict__ fcW, const float* __restrict__ fcb,
                     float* __restrict__ out) {
    int gw = (blockIdx.x * blockDim.x + threadIdx.x) >> 5;
    if (gw >= NN) return;
    int lane = threadIdx.x & 31;
    const float* h = g_h + (long)gw * D;
    float4 v = *(const float4*)(h + (lane << 2));
    int k0 = lane << 2;
    float4 w01 = __ldg((const float4*)(fcW + k0 * 2));
    float4 w23 = __ldg((const float4*)(fcW + k0 * 2 + 4));
    float a0 = v.x * w01.x + v.y * w01.z + v.z * w23.x + v.w * w23.z;
    float a1 = v.x * w01.y + v.y * w01.w + v.z * w23.y + v.w * w23.w;
    #pragma unroll
    for (int d2 = 16; d2; d2 >>= 1) {
        a0 += __shfl_xor_sync(0xffffffffu, a0, d2);
        a1 += __shfl_xor_sync(0xffffffffu, a1, d2);
    }
    if (lane == 0) {
        out[2 * gw]     = a0 + __ldg(&fcb[0]);
        out[2 * gw + 1] = a1 + __ldg(&fcb[1]);
    }
}

// ---------------- launch ----------------
extern "C" void kernel_launch(void* const* d_in, const int* in_sizes, int n_in,
                              void* d_out, int out_size) {
    const float* x   = (const float*)d_in[0];
    const int*   ei  = (const int*)d_in[1];
    const float* Wl  = (const float*)d_in[2];
    const float* Wr  = (const float*)d_in[3];
    const float* bl  = (const float*)d_in[4];
    const float* fcW = (const float*)d_in[5];
    const float* fcb = (const float*)d_in[6];
    float* out = (float*)d_out;

    const int smem_bytes = SM_TOT_BF * 2;  // 139264
    cudaFuncSetAttribute(k_gemm_mma, cudaFuncAttributeMaxDynamicSharedMemorySize, smem_bytes);

    k_zero_deg<<<SCAN_BLKS, 256>>>();
    k_count<<<(NE + 255) / 256, 256>>>(ei);
    k_prepw<<<(NL * 128 * 256 + 255) / 256, 256>>>(Wl, Wr);
    k_prepx<<<(NN * 32 + 255) / 256, 256>>>(x);
    k_scanA<<<SCAN_BLKS, 256>>>();
    k_scanB<<<1, 256>>>();
    k_scanC<<<SCAN_BLKS, 256>>>();
    k_fill<<<(NE + 255) / 256, 256>>>(ei);

    for (int l = 0; l < NL; l++) {
        k_agg<<<(NN * 32 + 255) / 256, 256>>>();
        k_gemm_mma<<<NTILES, 256, smem_bytes>>>(l, l < NL - 1, bl + (long)l * D);
    }
    k_fc<<<(NN * 32 + 255) / 256, 256>>>(fcW, fcb, out);
}

// round 13
// speedup vs baseline: 1.0096x; 1.0096x over previous
#include <cuda_runtime.h>
#include <cuda_bf16.h>
#include <cuda_fp16.h>
#include <cstdint>

#define NN 50000
#define NE 600000
#define D  128
#define NL 6
#define MT 128
#define NTILES ((NN + MT - 1) / MT)   // 391
#define SREG 136                      // smem row stride in bf16 (128 + 8 pad)
#define SCAN_BLKS ((NN + 255) / 256)  // 196

// ---------------- scratch (device globals; no allocation allowed) ----------------
__device__ float g_h[NN * D];                    // fp32 hidden (final layer only, for FC)
__device__ __half g_hf[NN * D];                  // fp16 hidden (gather operand, layers 1-5)
__device__ __nv_bfloat16 g_Ahi[NN * 256];        // A = [agg | h] bf16 hi
__device__ __nv_bfloat16 g_Alo[NN * 256];        // A lo residual
__device__ __nv_bfloat16 g_Bhi[NL * 128 * 256];  // B[n][k] = W[k][n], bf16 hi
__device__ __nv_bfloat16 g_Blo[NL * 128 * 256];  // lo residual
__device__ int g_rowptr[NN + 1];
__device__ int g_cursor[NN];
__device__ int g_deg[NN];
__device__ int g_esrc[NE];
__device__ int g_psum[256];                      // per-block partial sums (196 used)

// ---------------- helpers ----------------
__device__ __forceinline__ void mma16816(float* c, const uint32_t* a, const uint32_t* b) {
    asm volatile("mma.sync.aligned.m16n8k16.row.col.f32.bf16.bf16.f32 "
                 "{%0,%1,%2,%3}, {%4,%5,%6,%7}, {%8,%9}, {%0,%1,%2,%3};"
                 : "+f"(c[0]), "+f"(c[1]), "+f"(c[2]), "+f"(c[3])
                 : "r"(a[0]), "r"(a[1]), "r"(a[2]), "r"(a[3]), "r"(b[0]), "r"(b[1]));
}
__device__ __forceinline__ uint32_t pack_bf2(float x, float y) {
    __nv_bfloat162 h = __float22bfloat162_rn(make_float2(x, y));
    return *(uint32_t*)&h;
}
// split pair (x,y) -> hi packed, lo packed
__device__ __forceinline__ void split2(float x, float y, uint32_t& hi, uint32_t& lo) {
    __nv_bfloat16 hx = __float2bfloat16(x);
    __nv_bfloat16 hy = __float2bfloat16(y);
    hi = pack_bf2(x, y);
    lo = pack_bf2(x - __bfloat162float(hx), y - __bfloat162float(hy));
}

// ---------------- CSR construction ----------------
__global__ void k_count(const int* __restrict__ ei) {
    int i = blockIdx.x * blockDim.x + threadIdx.x;
    if (i < NE) atomicAdd(&g_deg[ei[NE + i]], 1);
}
// pass A: per-block totals of 256 degrees
__global__ void k_scanA() {
    __shared__ int ws[8];
    int tid = threadIdx.x, lane = tid & 31, wid = tid >> 5;
    int i = blockIdx.x * 256 + tid;
    int v = (i < NN) ? g_deg[i] : 0;
    #pragma unroll
    for (int d2 = 16; d2; d2 >>= 1) v += __shfl_xor_sync(0xffffffffu, v, d2);
    if (lane == 0) ws[wid] = v;
    __syncthreads();
    if (tid == 0) {
        int s = 0;
        #pragma unroll
        for (int j = 0; j < 8; j++) s += ws[j];
        g_psum[blockIdx.x] = s;
    }
}
// pass B: one block scans the partials into exclusive offsets
__global__ void k_scanB() {
    __shared__ int ws[8];
    int tid = threadIdx.x, lane = tid & 31, wid = tid >> 5;
    int v = (tid < SCAN_BLKS) ? g_psum[tid] : 0;
    int incl = v;
    #pragma unroll
    for (int d2 = 1; d2 < 32; d2 <<= 1) {
        int t = __shfl_up_sync(0xffffffffu, incl, d2);
        if (lane >= d2) incl += t;
    }
    if (lane == 31) ws[wid] = incl;
    __syncthreads();
    if (wid == 0 && lane < 8) {
        int s = ws[lane];
        int x2 = s;
        #pragma unroll
        for (int d2 = 1; d2 < 8; d2 <<= 1) {
            int t = __shfl_up_sync(0xffu, x2, d2);
            if (lane >= d2) x2 += t;
        }
        ws[lane] = x2 - s;   // exclusive warp offsets
    }
    __syncthreads();
    if (tid < SCAN_BLKS) g_psum[tid] = incl - v + ws[wid];  // exclusive prefix
    if (tid == 0) g_rowptr[0] = 0;
}
// pass C: intra-block scan + block offset -> rowptr, cursor; re-zeroes deg for next replay
__global__ void k_scanC() {
    __shared__ int ws[8];
    int tid = threadIdx.x, lane = tid & 31, wid = tid >> 5;
    int i = blockIdx.x * 256 + tid;
    int v = (i < NN) ? g_deg[i] : 0;
    int incl = v;
    #pragma unroll
    for (int d2 = 1; d2 < 32; d2 <<= 1) {
        int t = __shfl_up_sync(0xffffffffu, incl, d2);
        if (lane >= d2) incl += t;
    }
    if (lane == 31) ws[wid] = incl;
    __syncthreads();
    if (wid == 0 && lane < 8) {
        int s = ws[lane];
        int x2 = s;
        #pragma unroll
        for (int d2 = 1; d2 < 8; d2 <<= 1) {
            int t = __shfl_up_sync(0xffu, x2, d2);
            if (lane >= d2) x2 += t;
        }
        ws[lane] = x2 - s;
    }
    __syncthreads();
    if (i < NN) {
        int base = g_psum[blockIdx.x] + ws[wid];
        g_rowptr[i + 1] = base + incl;
        g_cursor[i] = base + incl - v;
        g_deg[i] = 0;   // prime next replay (module-load zeros cover replay 1)
    }
}
__global__ void k_fill(const int* __restrict__ ei) {
    int i = blockIdx.x * blockDim.x + threadIdx.x;
    if (i < NE) {
        int dst = ei[NE + i];
        int pos = atomicAdd(&g_cursor[dst], 1);
        g_esrc[pos] = ei[i];
    }
}

// ---------------- weight transpose + split (once per launch) ----------------
__global__ void k_prepw(const float* __restrict__ Wl, const float* __restrict__ Wr) {
    int idx = blockIdx.x * blockDim.x + threadIdx.x;
    if (idx >= NL * 128 * 256) return;
    int l = idx >> 15;
    int r = idx & 32767;
    int n = r >> 8;
    int k = r & 255;
    const float* W = (k < D) ? (Wl + (long)l * D * D) : (Wr + (long)l * D * D);
    float v = __ldg(&W[(k & 127) * D + n]);
    __nv_bfloat16 hi = __float2bfloat16(v);
    g_Bhi[idx] = hi;
    g_Blo[idx] = __float2bfloat16(v - __bfloat162float(hi));
}

// ---------------- mean aggregation: warp per node, writes split A cols [0,128) ----------------
// layer 0 gathers fp32 x (and also splits x into A cols [128,256)); layers >=1 gather fp16 g_hf.
// Unroll-8 with batched index prefetch for MLP. (R11-proven form.)
__global__ void k_agg(const float* __restrict__ x, int use_x) {
    int gw = (blockIdx.x * blockDim.x + threadIdx.x) >> 5;
    if (gw >= NN) return;
    int lane = threadIdx.x & 31;
    int off = lane << 2;
    int beg = g_rowptr[gw], end = g_rowptr[gw + 1];
    float ax = 0.f, ay = 0.f, az = 0.f, aw = 0.f;
    if (use_x) {
        int e = beg;
        for (; e + 8 <= end; e += 8) {
            int idx[8];
            #pragma unroll
            for (int j = 0; j < 8; j++) idx[j] = __ldg(&g_esrc[e + j]);
            float4 v[8];
            #pragma unroll
            for (int j = 0; j < 8; j++)
                v[j] = __ldg((const float4*)(x + (long)idx[j] * D + off));
            #pragma unroll
            for (int j = 0; j < 8; j++) {
                ax += v[j].x; ay += v[j].y; az += v[j].z; aw += v[j].w;
            }
        }
        for (; e < end; ++e) {
            int s0 = __ldg(&g_esrc[e]);
            float4 v0 = __ldg((const float4*)(x + (long)s0 * D + off));
            ax += v0.x; ay += v0.y; az += v0.z; aw += v0.w;
        }
    } else {
        int e = beg;
        for (; e + 8 <= end; e += 8) {
            int idx[8];
            #pragma unroll
            for (int j = 0; j < 8; j++) idx[j] = __ldg(&g_esrc[e + j]);
            uint2 u[8];
            #pragma unroll
            for (int j = 0; j < 8; j++)
                u[j] = __ldg((const uint2*)(g_hf + (long)idx[j] * D) + lane);
            #pragma unroll
            for (int j = 0; j < 8; j++) {
                float2 a = __half22float2(*(__half2*)&u[j].x);
                float2 b = __half22float2(*(__half2*)&u[j].y);
                ax += a.x; ay += a.y; az += b.x; aw += b.y;
            }
        }
        for (; e < end; ++e) {
            int s0 = __ldg(&g_esrc[e]);
            uint2 u0 = __ldg((const uint2*)(g_hf + (long)s0 * D) + lane);
            float2 a = __half22float2(*(__half2*)&u0.x);
            float2 b = __half22float2(*(__half2*)&u0.y);
            ax += a.x; ay += a.y; az += b.x; aw += b.y;
        }
    }
    float inv = 1.0f / fmaxf((float)(end - beg), 1.0f);
    ax *= inv; ay *= inv; az *= inv; aw *= inv;
    uint32_t h0, l0, h1, l1;
    split2(ax, ay, h0, l0);
    split2(az, aw, h1, l1);
    uint32_t* ph = (uint32_t*)(g_Ahi + (long)gw * 256 + off);
    uint32_t* pl = (uint32_t*)(g_Alo + (long)gw * 256 + off);
    ph[0] = h0; ph[1] = h1;
    pl[0] = l0; pl[1] = l1;
    if (use_x) {
        // fold former k_splitx: write A cols [128,256) from x (coalesced)
        float4 xv = __ldg((const float4*)(x + (long)gw * D + off));
        uint32_t xh0, xl0, xh1, xl1;
        split2(xv.x, xv.y, xh0, xl0);
        split2(xv.z, xv.w, xh1, xl1);
        uint32_t* phx = (uint32_t*)(g_Ahi + (long)gw * 256 + 128 + off);
        uint32_t* plx = (uint32_t*)(g_Alo + (long)gw * 256 + 128 + off);
        phx[0] = xh0; phx[1] = xh1;
        plx[0] = xl0; plx[1] = xl1;
    }
}

// ---------------- tensor-core GEMM: h = relu(A @ B^T + bl) ----------------
// 256 threads = 8 warps, warp grid 2(m) x 4(n), warp tile 64x32, frag m16n8k16.
// 3-term bf16 split: hihi + hilo + lohi. Direct LDS.32 fragment loads (R6-proven).
#define SM_A_HI 0
#define SM_A_LO (128 * SREG)
#define SM_B_HI (2 * 128 * SREG)
#define SM_B_LO (3 * 128 * SREG)
#define SM_TOT_BF (4 * 128 * SREG)   // 69632 bf16 = 139264 bytes

__global__ void __launch_bounds__(256, 1)
k_gemm_mma(int layer, int write_split, const float* __restrict__ bl) {
    extern __shared__ __nv_bfloat16 smem[];
    __nv_bfloat16* sAhi = smem + SM_A_HI;
    __nv_bfloat16* sAlo = smem + SM_A_LO;
    __nv_bfloat16* sBhi = smem + SM_B_HI;
    __nv_bfloat16* sBlo = smem + SM_B_LO;

    int tid = threadIdx.x;
    int lane = tid & 31, wid = tid >> 5;
    int warp_m = wid >> 2, warp_n = wid & 3;
    int m0 = blockIdx.x * MT;
    int g = lane >> 2, t = lane & 3;

    float acc[4][4][4];
    #pragma unroll
    for (int i = 0; i < 4; i++)
        #pragma unroll
        for (int j = 0; j < 4; j++)
            #pragma unroll
            for (int p = 0; p < 4; p++) acc[i][j][p] = 0.f;

    const __nv_bfloat16* gB_hi = g_Bhi + (long)layer * 128 * 256;
    const __nv_bfloat16* gB_lo = g_Blo + (long)layer * 128 * 256;

    #pragma unroll 1
    for (int chunk = 0; chunk < 2; chunk++) {
        int kbase = chunk << 7;
        if (chunk) __syncthreads();
        // stage A hi/lo (row-guarded) and B hi/lo, 16B per thread per iter
        #pragma unroll
        for (int i = 0; i < 8; i++) {
            int lin = tid + i * 256;
            int row = lin >> 4;
            int c8 = (lin & 15) << 3;
            uint4 vh = make_uint4(0, 0, 0, 0), vl = vh;
            int gr = m0 + row;
            if (gr < NN) {
                vh = *(const uint4*)(g_Ahi + (long)gr * 256 + kbase + c8);
                vl = *(const uint4*)(g_Alo + (long)gr * 256 + kbase + c8);
            }
            *(uint4*)(sAhi + row * SREG + c8) = vh;
            *(uint4*)(sAlo + row * SREG + c8) = vl;
            uint4 bh = *(const uint4*)(gB_hi + (long)row * 256 + kbase + c8);
            uint4 blv = *(const uint4*)(gB_lo + (long)row * 256 + kbase + c8);
            *(uint4*)(sBhi + row * SREG + c8) = bh;
            *(uint4*)(sBlo + row * SREG + c8) = blv;
        }
        __syncthreads();

        #pragma unroll
        for (int ks = 0; ks < 8; ks++) {
            int kcol = (ks << 4) + (t << 1);
            uint32_t ahi[4][4], alo[4][4];
            #pragma unroll
            for (int mf = 0; mf < 4; mf++) {
                int r = warp_m * 64 + mf * 16 + g;
                ahi[mf][0] = *(const uint32_t*)(sAhi + r * SREG + kcol);
                ahi[mf][1] = *(const uint32_t*)(sAhi + (r + 8) * SREG + kcol);
                ahi[mf][2] = *(const uint32_t*)(sAhi + r * SREG + kcol + 8);
                ahi[mf][3] = *(const uint32_t*)(sAhi + (r + 8) * SREG + kcol + 8);
                alo[mf][0] = *(const uint32_t*)(sAlo + r * SREG + kcol);
                alo[mf][1] = *(const uint32_t*)(sAlo + (r + 8) * SREG + kcol);
                alo[mf][2] = *(const uint32_t*)(sAlo + r * SREG + kcol + 8);
                alo[mf][3] = *(const uint32_t*)(sAlo + (r + 8) * SREG + kcol + 8);
            }
            uint32_t bhi[4][2], blo[4][2];
            #pragma unroll
            for (int nf = 0; nf < 4; nf++) {
                int nr = warp_n * 32 + nf * 8 + g;
                bhi[nf][0] = *(const uint32_t*)(sBhi + nr * SREG + kcol);
                bhi[nf][1] = *(const uint32_t*)(sBhi + nr * SREG + kcol + 8);
                blo[nf][0] = *(const uint32_t*)(sBlo + nr * SREG + kcol);
                blo[nf][1] = *(const uint32_t*)(sBlo + nr * SREG + kcol + 8);
            }
            #pragma unroll
            for (int mf = 0; mf < 4; mf++)
                #pragma unroll
                for (int nf = 0; nf < 4; nf++) {
                    mma16816(acc[mf][nf], ahi[mf], bhi[nf]);
                    mma16816(acc[mf][nf], ahi[mf], blo[nf]);
                    mma16816(acc[mf][nf], alo[mf], bhi[nf]);
                }
        }
    }

    // epilogue: bias + relu.
    // layers 0-4 (write_split): store fp16 gather copy + bf16 split A cols [128,256)
    // last layer: store fp32 g_h for the FC
    #pragma unroll
    for (int nf = 0; nf < 4; nf++) {
        int col = warp_n * 32 + nf * 8 + (t << 1);
        float b0 = __ldg(&bl[col]);
        float b1 = __ldg(&bl[col + 1]);
        #pragma unroll
        for (int mf = 0; mf < 4; mf++) {
            int r0 = m0 + warp_m * 64 + mf * 16 + g;
            #pragma unroll
            for (int half = 0; half < 2; half++) {
                int r = r0 + half * 8;
                if (r < NN) {
                    float o0 = fmaxf(acc[mf][nf][half * 2 + 0] + b0, 0.f);
                    float o1 = fmaxf(acc[mf][nf][half * 2 + 1] + b1, 0.f);
                    if (write_split) {
                        __half2 hf = __float22half2_rn(make_float2(o0, o1));
                        *(uint32_t*)(g_hf + (long)r * D + col) = *(uint32_t*)&hf;
                        uint32_t hp, lp;
                        split2(o0, o1, hp, lp);
                        *(uint32_t*)(g_Ahi + (long)r * 256 + 128 + col) = hp;
                        *(uint32_t*)(g_Alo + (long)r * 256 + 128 + col) = lp;
                    } else {
                        *(float2*)(g_h + (long)r * D + col) = make_float2(o0, o1);
                    }
                }
            }
        }
    }
}

// ---------------- final FC [128 -> 2]: warp per node ----------------
__global__ void k_fc(const float* __restrict__ fcW, const float* __restrict__ fcb,
                     float* __restrict__ out) {
    int gw = (blockIdx.x * blockDim.x + threadIdx.x) >> 5;
    if (gw >= NN) return;
    int lane = threadIdx.x & 31;
    const float* h = g_h + (long)gw * D;
    float4 v = *(const float4*)(h + (lane << 2));
    int k0 = lane << 2;
    float4 w01 = __ldg((const float4*)(fcW + k0 * 2));
    float4 w23 = __ldg((const float4*)(fcW + k0 * 2 + 4));
    float a0 = v.x * w01.x + v.y * w01.z + v.z * w23.x + v.w * w23.z;
    float a1 = v.x * w01.y + v.y * w01.w + v.z * w23.y + v.w * w23.w;
    #pragma unroll
    for (int d2 = 16; d2; d2 >>= 1) {
        a0 += __shfl_xor_sync(0xffffffffu, a0, d2);
        a1 += __shfl_xor_sync(0xffffffffu, a1, d2);
    }
    if (lane == 0) {
        out[2 * gw]     = a0 + __ldg(&fcb[0]);
        out[2 * gw + 1] = a1 + __ldg(&fcb[1]);
    }
}

// ---------------- launch ----------------
extern "C" void kernel_launch(void* const* d_in, const int* in_sizes, int n_in,
                              void* d_out, int out_size) {
    const float* x   = (const float*)d_in[0];
    const int*   ei  = (const int*)d_in[1];
    const float* Wl  = (const float*)d_in[2];
    const float* Wr  = (const float*)d_in[3];
    const float* bl  = (const float*)d_in[4];
    const float* fcW = (const float*)d_in[5];
    const float* fcb = (const float*)d_in[6];
    float* out = (float*)d_out;

    const int smem_bytes = SM_TOT_BF * 2;  // 139264
    cudaFuncSetAttribute(k_gemm_mma, cudaFuncAttributeMaxDynamicSharedMemorySize, smem_bytes);

    // launch #1..#3
    k_count<<<(NE + 255) / 256, 256>>>(ei);
    k_prepw<<<(NL * 128 * 256 + 255) / 256, 256>>>(Wl, Wr);
    k_scanA<<<SCAN_BLKS, 256>>>();
    // launch #4 — PROFILING PROBE: fp16-path agg on stale-but-deterministic state.
    // Replay 1: rowptr/esrc/g_hf are zeros -> no-op writes. Replay >=2: realistic
    // gather workload (prior-replay CSR + hidden). All outputs overwritten by the
    // real layer-0 k_agg below before any consumer. ncu (-s -> 4th launch) now
    // reports k_agg's true roofline instead of a setup kernel.
    k_agg<<<(NN * 32 + 255) / 256, 256>>>(x, 0);
    // remaining CSR build
    k_scanB<<<1, 256>>>();
    k_scanC<<<SCAN_BLKS, 256>>>();
    k_fill<<<(NE + 255) / 256, 256>>>(ei);

    for (int l = 0; l < NL; l++) {
        k_agg<<<(NN * 32 + 255) / 256, 256>>>(x, l == 0);
        k_gemm_mma<<<NTILES, 256, smem_bytes>>>(l, l < NL - 1, bl + (long)l * D);
    }
    k_fc<<<(NN * 32 + 255) / 256, 256>>>(fcW, fcb, out);
}

// round 17
// speedup vs baseline: 1.4592x; 1.4453x over previous
#include <cuda_runtime.h>
#include <cuda_fp16.h>
#include <cstdint>

#define NN 50000
#define NE 600000
#define D  128
#define NL 6
#define MT 128
#define NTILES ((NN + MT - 1) / MT)   // 391
#define SREG 136                      // smem row stride in halfs (128 + 8 pad)
#define SCAN_BLKS ((NN + 255) / 256)  // 196

// ---------------- scratch (device globals; no allocation allowed) ----------------
__device__ float  g_h[NN * D];             // fp32 hidden (final layer only, for FC)
__device__ __half g_hf[NN * D];            // fp16 h   (gather + GEMM A cols [128,256))
__device__ __half g_af[NN * D];            // fp16 agg (GEMM A cols [0,128))
__device__ __half g_Whi[NL * 128 * 256];   // B[n][k] = W[k][n], fp16 hi
__device__ __half g_Wlo[NL * 128 * 256];   // fp16 lo residual (W exact to ~2^-21)
__device__ int g_rowptr[NN + 1];
__device__ int g_cursor[NN];
__device__ int g_deg[NN];
__device__ int g_esrc[NE];
__device__ int g_psum[256];

// ---------------- helpers ----------------
__device__ __forceinline__ void mma16816h(float* c, const uint32_t* a, const uint32_t* b) {
    asm volatile("mma.sync.aligned.m16n8k16.row.col.f32.f16.f16.f32 "
                 "{%0,%1,%2,%3}, {%4,%5,%6,%7}, {%8,%9}, {%0,%1,%2,%3};"
                 : "+f"(c[0]), "+f"(c[1]), "+f"(c[2]), "+f"(c[3])
                 : "r"(a[0]), "r"(a[1]), "r"(a[2]), "r"(a[3]), "r"(b[0]), "r"(b[1]));
}
__device__ __forceinline__ uint32_t pack_h2(float x, float y) {
    __half2 h = __float22half2_rn(make_float2(x, y));
    return *(uint32_t*)&h;
}

// ---------------- CSR construction ----------------
__global__ void k_count(const int* __restrict__ ei) {
    int i = blockIdx.x * blockDim.x + threadIdx.x;
    if (i < NE) atomicAdd(&g_deg[ei[NE + i]], 1);
}
__global__ void k_scanA() {
    __shared__ int ws[8];
    int tid = threadIdx.x, lane = tid & 31, wid = tid >> 5;
    int i = blockIdx.x * 256 + tid;
    int v = (i < NN) ? g_deg[i] : 0;
    #pragma unroll
    for (int d2 = 16; d2; d2 >>= 1) v += __shfl_xor_sync(0xffffffffu, v, d2);
    if (lane == 0) ws[wid] = v;
    __syncthreads();
    if (tid == 0) {
        int s = 0;
        #pragma unroll
        for (int j = 0; j < 8; j++) s += ws[j];
        g_psum[blockIdx.x] = s;
    }
}
__global__ void k_scanB() {
    __shared__ int ws[8];
    int tid = threadIdx.x, lane = tid & 31, wid = tid >> 5;
    int v = (tid < SCAN_BLKS) ? g_psum[tid] : 0;
    int incl = v;
    #pragma unroll
    for (int d2 = 1; d2 < 32; d2 <<= 1) {
        int t = __shfl_up_sync(0xffffffffu, incl, d2);
        if (lane >= d2) incl += t;
    }
    if (lane == 31) ws[wid] = incl;
    __syncthreads();
    if (wid == 0 && lane < 8) {
        int s = ws[lane];
        int x2 = s;
        #pragma unroll
        for (int d2 = 1; d2 < 8; d2 <<= 1) {
            int t = __shfl_up_sync(0xffu, x2, d2);
            if (lane >= d2) x2 += t;
        }
        ws[lane] = x2 - s;
    }
    __syncthreads();
    if (tid < SCAN_BLKS) g_psum[tid] = incl - v + ws[wid];
    if (tid == 0) g_rowptr[0] = 0;
}
// pass C: rowptr + cursor; re-zeroes deg for next replay
__global__ void k_scanC() {
    __shared__ int ws[8];
    int tid = threadIdx.x, lane = tid & 31, wid = tid >> 5;
    int i = blockIdx.x * 256 + tid;
    int v = (i < NN) ? g_deg[i] : 0;
    int incl = v;
    #pragma unroll
    for (int d2 = 1; d2 < 32; d2 <<= 1) {
        int t = __shfl_up_sync(0xffffffffu, incl, d2);
        if (lane >= d2) incl += t;
    }
    if (lane == 31) ws[wid] = incl;
    __syncthreads();
    if (wid == 0 && lane < 8) {
        int s = ws[lane];
        int x2 = s;
        #pragma unroll
        for (int d2 = 1; d2 < 8; d2 <<= 1) {
            int t = __shfl_up_sync(0xffu, x2, d2);
            if (lane >= d2) x2 += t;
        }
        ws[lane] = x2 - s;
    }
    __syncthreads();
    if (i < NN) {
        int base = g_psum[blockIdx.x] + ws[wid];
        g_rowptr[i + 1] = base + incl;
        g_cursor[i] = base + incl - v;
        g_deg[i] = 0;   // prime next replay (module-load zeros cover replay 1)
    }
}
__global__ void k_fill(const int* __restrict__ ei) {
    int i = blockIdx.x * blockDim.x + threadIdx.x;
    if (i < NE) {
        int dst = ei[NE + i];
        int pos = atomicAdd(&g_cursor[dst], 1);
        g_esrc[pos] = ei[i];
    }
}

// ---------------- weight transpose + fp16 hi/lo split (once per launch) ----------------
__global__ void k_prepw(const float* __restrict__ Wl, const float* __restrict__ Wr) {
    int idx = blockIdx.x * blockDim.x + threadIdx.x;
    if (idx >= NL * 128 * 256) return;
    int l = idx >> 15;
    int r = idx & 32767;
    int n = r >> 8;
    int k = r & 255;
    const float* W = (k < D) ? (Wl + (long)l * D * D) : (Wr + (long)l * D * D);
    float v = __ldg(&W[(k & 127) * D + n]);
    __half hi = __float2half_rn(v);
    g_Whi[idx] = hi;
    g_Wlo[idx] = __float2half_rn(v - __half2float(hi));
}

// ---------------- mean aggregation: warp per node ----------------
// layer 0: gathers fp32 x, also writes g_hf[gw] = fp16(x row).
// layers >=1: gathers fp16 g_hf. Result -> g_af fp16. Unroll-8 batched prefetch.
__global__ void k_agg(const float* __restrict__ x, int use_x) {
    int gw = (blockIdx.x * blockDim.x + threadIdx.x) >> 5;
    if (gw >= NN) return;
    int lane = threadIdx.x & 31;
    int off = lane << 2;
    int beg = g_rowptr[gw], end = g_rowptr[gw + 1];
    float ax = 0.f, ay = 0.f, az = 0.f, aw = 0.f;
    if (use_x) {
        int e = beg;
        for (; e + 8 <= end; e += 8) {
            int idx[8];
            #pragma unroll
            for (int j = 0; j < 8; j++) idx[j] = __ldg(&g_esrc[e + j]);
            float4 v[8];
            #pragma unroll
            for (int j = 0; j < 8; j++)
                v[j] = __ldg((const float4*)(x + (long)idx[j] * D + off));
            #pragma unroll
            for (int j = 0; j < 8; j++) {
                ax += v[j].x; ay += v[j].y; az += v[j].z; aw += v[j].w;
            }
        }
        for (; e < end; ++e) {
            int s0 = __ldg(&g_esrc[e]);
            float4 v0 = __ldg((const float4*)(x + (long)s0 * D + off));
            ax += v0.x; ay += v0.y; az += v0.z; aw += v0.w;
        }
    } else {
        int e = beg;
        for (; e + 8 <= end; e += 8) {
            int idx[8];
            #pragma unroll
            for (int j = 0; j < 8; j++) idx[j] = __ldg(&g_esrc[e + j]);
            uint2 u[8];
            #pragma unroll
            for (int j = 0; j < 8; j++)
                u[j] = __ldg((const uint2*)(g_hf + (long)idx[j] * D) + lane);
            #pragma unroll
            for (int j = 0; j < 8; j++) {
                float2 a = __half22float2(*(__half2*)&u[j].x);
                float2 b = __half22float2(*(__half2*)&u[j].y);
                ax += a.x; ay += a.y; az += b.x; aw += b.y;
            }
        }
        for (; e < end; ++e) {
            int s0 = __ldg(&g_esrc[e]);
            uint2 u0 = __ldg((const uint2*)(g_hf + (long)s0 * D) + lane);
            float2 a = __half22float2(*(__half2*)&u0.x);
            float2 b = __half22float2(*(__half2*)&u0.y);
            ax += a.x; ay += a.y; az += b.x; aw += b.y;
        }
    }
    float inv = 1.0f / fmaxf((float)(end - beg), 1.0f);
    uint32_t* pa = (uint32_t*)(g_af + (long)gw * D + off);
    pa[0] = pack_h2(ax * inv, ay * inv);
    pa[1] = pack_h2(az * inv, aw * inv);
    if (use_x) {
        float4 xv = __ldg((const float4*)(x + (long)gw * D + off));
        uint32_t* pf = (uint32_t*)(g_hf + (long)gw * D + off);
        pf[0] = pack_h2(xv.x, xv.y);
        pf[1] = pack_h2(xv.z, xv.w);
    }
}

// ---------------- tensor-core GEMM: h = relu([af|hf] @ [Whi+Wlo]^T + bl) ----------------
// 256 threads = 8 warps, warp grid 2(m) x 4(n), warp tile 64x32, frag m16n8k16 fp16.
// 2-term split: A*Bhi + A*Blo (A fp16-rounded; B exact to ~2^-21).
#define SM_A    0
#define SM_B_HI (128 * SREG)
#define SM_B_LO (2 * 128 * SREG)
#define SM_TOT_H (3 * 128 * SREG)   // 52224 halfs = 104448 bytes

__global__ void __launch_bounds__(256, 2)
k_gemm_mma(int layer, int write_split, const float* __restrict__ bl) {
    extern __shared__ __half smem[];
    __half* sA   = smem + SM_A;
    __half* sBhi = smem + SM_B_HI;
    __half* sBlo = smem + SM_B_LO;

    int tid = threadIdx.x;
    int lane = tid & 31, wid = tid >> 5;
    int warp_m = wid >> 2, warp_n = wid & 3;
    int m0 = blockIdx.x * MT;
    int g = lane >> 2, t = lane & 3;

    float acc[4][4][4];
    #pragma unroll
    for (int i = 0; i < 4; i++)
        #pragma unroll
        for (int j = 0; j < 4; j++)
            #pragma unroll
            for (int p = 0; p < 4; p++) acc[i][j][p] = 0.f;

    const __half* gW_hi = g_Whi + (long)layer * 128 * 256;
    const __half* gW_lo = g_Wlo + (long)layer * 128 * 256;

    #pragma unroll 1
    for (int chunk = 0; chunk < 2; chunk++) {
        int kbase = chunk << 7;
        if (chunk) __syncthreads();
        const __half* gA = chunk ? g_hf : g_af;   // A cols [0,128)=agg, [128,256)=h
        #pragma unroll
        for (int i = 0; i < 8; i++) {
            int lin = tid + i * 256;
            int row = lin >> 4;
            int c8 = (lin & 15) << 3;       // half index within 128-col row
            uint4 va = make_uint4(0, 0, 0, 0);
            int gr = m0 + row;
            if (gr < NN) va = *(const uint4*)(gA + (long)gr * D + c8);
            *(uint4*)(sA + row * SREG + c8) = va;
            uint4 bh  = *(const uint4*)(gW_hi + (long)row * 256 + kbase + c8);
            uint4 blv = *(const uint4*)(gW_lo + (long)row * 256 + kbase + c8);
            *(uint4*)(sBhi + row * SREG + c8) = bh;
            *(uint4*)(sBlo + row * SREG + c8) = blv;
        }
        __syncthreads();

        #pragma unroll
        for (int ks = 0; ks < 8; ks++) {
            int kcol = (ks << 4) + (t << 1);
            uint32_t a[4][4];
            #pragma unroll
            for (int mf = 0; mf < 4; mf++) {
                int r = warp_m * 64 + mf * 16 + g;
                a[mf][0] = *(const uint32_t*)(sA + r * SREG + kcol);
                a[mf][1] = *(const uint32_t*)(sA + (r + 8) * SREG + kcol);
                a[mf][2] = *(const uint32_t*)(sA + r * SREG + kcol + 8);
                a[mf][3] = *(const uint32_t*)(sA + (r + 8) * SREG + kcol + 8);
            }
            uint32_t bhi[4][2], blo[4][2];
            #pragma unroll
            for (int nf = 0; nf < 4; nf++) {
                int nr = warp_n * 32 + nf * 8 + g;
                bhi[nf][0] = *(const uint32_t*)(sBhi + nr * SREG + kcol);
                bhi[nf][1] = *(const uint32_t*)(sBhi + nr * SREG + kcol + 8);
                blo[nf][0] = *(const uint32_t*)(sBlo + nr * SREG + kcol);
                blo[nf][1] = *(const uint32_t*)(sBlo + nr * SREG + kcol + 8);
            }
            #pragma unroll
            for (int mf = 0; mf < 4; mf++)
                #pragma unroll
                for (int nf = 0; nf < 4; nf++) {
                    mma16816h(acc[mf][nf], a[mf], bhi[nf]);
                    mma16816h(acc[mf][nf], a[mf], blo[nf]);
                }
        }
    }

    // epilogue: bias + relu. layers 0-4: fp16 -> g_hf; last layer: fp32 -> g_h.
    #pragma unroll
    for (int nf = 0; nf < 4; nf++) {
        int col = warp_n * 32 + nf * 8 + (t << 1);
        float b0 = __ldg(&bl[col]);
        float b1 = __ldg(&bl[col + 1]);
        #pragma unroll
        for (int mf = 0; mf < 4; mf++) {
            int r0 = m0 + warp_m * 64 + mf * 16 + g;
            #pragma unroll
            for (int half = 0; half < 2; half++) {
                int r = r0 + half * 8;
                if (r < NN) {
                    float o0 = fmaxf(acc[mf][nf][half * 2 + 0] + b0, 0.f);
                    float o1 = fmaxf(acc[mf][nf][half * 2 + 1] + b1, 0.f);
                    if (write_split) {
                        *(uint32_t*)(g_hf + (long)r * D + col) = pack_h2(o0, o1);
                    } else {
                        *(float2*)(g_h + (long)r * D + col) = make_float2(o0, o1);
                    }
                }
            }
        }
    }
}

// ---------------- final FC [128 -> 2]: warp per node ----------------
__global__ void k_fc(const float* __restrict__ fcW, const float* __restrict__ fcb,
                     float* __restrict__ out) {
    int gw = (blockIdx.x * blockDim.x + threadIdx.x) >> 5;
    if (gw >= NN) return;
    int lane = threadIdx.x & 31;
    const float* h = g_h + (long)gw * D;
    float4 v = *(const float4*)(h + (lane << 2));
    int k0 = lane << 2;
    float4 w01 = __ldg((const float4*)(fcW + k0 * 2));
    float4 w23 = __ldg((const float4*)(fcW + k0 * 2 + 4));
    float a0 = v.x * w01.x + v.y * w01.z + v.z * w23.x + v.w * w23.z;
    float a1 = v.x * w01.y + v.y * w01.w + v.z * w23.y + v.w * w23.w;
    #pragma unroll
    for (int d2 = 16; d2; d2 >>= 1) {
        a0 += __shfl_xor_sync(0xffffffffu, a0, d2);
        a1 += __shfl_xor_sync(0xffffffffu, a1, d2);
    }
    if (lane == 0) {
        out[2 * gw]     = a0 + __ldg(&fcb[0]);
        out[2 * gw + 1] = a1 + __ldg(&fcb[1]);
    }
}

// ---------------- launch ----------------
extern "C" void kernel_launch(void* const* d_in, const int* in_sizes, int n_in,
                              void* d_out, int out_size) {
    const float* x   = (const float*)d_in[0];
    const int*   ei  = (const int*)d_in[1];
    const float* Wl  = (const float*)d_in[2];
    const float* Wr  = (const float*)d_in[3];
    const float* bl  = (const float*)d_in[4];
    const float* fcW = (const float*)d_in[5];
    const float* fcb = (const float*)d_in[6];
    float* out = (float*)d_out;

    const int smem_bytes = SM_TOT_H * 2;  // 104448
    cudaFuncSetAttribute(k_gemm_mma, cudaFuncAttributeMaxDynamicSharedMemorySize, smem_bytes);

    k_count<<<(NE + 255) / 256, 256>>>(ei);
    k_prepw<<<(NL * 128 * 256 + 255) / 256, 256>>>(Wl, Wr);
    k_scanA<<<SCAN_BLKS, 256>>>();
    k_scanB<<<1, 256>>>();
    k_scanC<<<SCAN_BLKS, 256>>>();
    k_fill<<<(NE + 255) / 256, 256>>>(ei);

    for (int l = 0; l < NL; l++) {
        k_agg<<<(NN * 32 + 255) / 256, 256>>>(x, l == 0);
        k_gemm_mma<<<NTILES, 256, smem_bytes>>>(l, l < NL - 1, bl + (long)l * D);
    }
    k_fc<<<(NN * 32 + 255) / 256, 256>>>(fcW, fcb, out);
}